// round 1
// baseline (speedup 1.0000x reference)
#include <cuda_runtime.h>
#include <cstdint>

// Problem constants
#define Hh   128
#define Wd   128
#define HWsz 16384
#define Cc   64
#define Bb   8
#define NPIX (Bb * HWsz)   // 131072 pixels total

// -------- scratch (__device__ globals: no allocation allowed) --------
__device__ float  g_xt[(size_t)NPIX * Cc];     // x transposed to [b*HW + hw][c]  (NHWC)
__device__ float  g_wq[576 * 64];              // w_conv repacked: [(c*9+k)][o]
__device__ int4   g_ci[(size_t)NPIX * 9];      // 4 clamped corner spatial indices per (pixel, tap)
__device__ float4 g_cw[(size_t)NPIX * 9];      // 4 corner weights (mask*validity folded in)

// ---------------- kernel 1: NCHW -> NHWC transpose ----------------
__global__ void __launch_bounds__(256) k_transpose(const float* __restrict__ x) {
    __shared__ float sh[64][33];
    int blk = blockIdx.x;            // 4096 blocks; 512 tiles per batch
    int b   = blk >> 9;
    int hw0 = (blk & 511) << 5;      // 32 hw positions per tile
    int t = threadIdx.x;
#pragma unroll
    for (int i = 0; i < 8; i++) {
        int e = t + i * 256;
        int c = e >> 5, wp = e & 31;
        sh[c][wp] = x[((size_t)(b * 64 + c) << 14) + hw0 + wp];
    }
    __syncthreads();
#pragma unroll
    for (int i = 0; i < 8; i++) {
        int e = t + i * 256;
        int wp = e >> 6, c = e & 63;
        g_xt[(((size_t)b << 14) + hw0 + wp) * 64 + c] = sh[c][wp];
    }
}

// ---------------- kernel 2: repack w_conv ----------------
// w_conv flat: [o][c][k] (o*576 + c*9 + k)  ->  g_wq[(c*9+k)*64 + o]
__global__ void k_wq(const float* __restrict__ w_conv) {
    int t = blockIdx.x * 256 + threadIdx.x;
    if (t < 64 * 576) {
        int o   = t / 576;
        int rem = t - o * 576;       // = c*9 + k
        g_wq[rem * 64 + o] = w_conv[t];
    }
}

// ---------------- kernel 3: offset+mask conv + corner precompute ----------------
// Each thread: 2 pixels (p0 and p0+128, same column, adjacent rows).
// 27 output channels: 0..17 = offsets (y,x interleaved per tap), 18..26 = mask logits.
__global__ void __launch_bounds__(128) k_conv(const float* __restrict__ x,
                                              const float* __restrict__ w_off,
                                              const float* __restrict__ w_msk) {
    extern __shared__ float shW[];   // 27*576 floats = 62208 B
    int t = threadIdx.x;
    for (int i = t; i < 18 * 576; i += 128) shW[i] = w_off[i];
    for (int i = t; i < 9 * 576; i += 128) shW[18 * 576 + i] = w_msk[i];
    __syncthreads();

    int p0  = blockIdx.x * 256 + t;  // 512 blocks * 256 px, 128 threads, 2 px/thread
    int b   = p0 >> 14;
    int hw0 = p0 & 16383;
    int h0  = hw0 >> 7, w0c = hw0 & 127;
    int h1  = h0 + 1;                // pixel 1 = p0 + 128 (next row, same col, same batch)
    const float* xb = x + (((size_t)b << 6) << 14);

    float a0[27], a1[27];
#pragma unroll
    for (int i = 0; i < 27; i++) { a0[i] = 0.f; a1[i] = 0.f; }

#pragma unroll 1
    for (int kk = 0; kk < 9; kk++) {
        int dy = kk / 3 - 1, dx = kk % 3 - 1;
        int hh0 = h0 + dy, ww = w0c + dx;
        int hh1 = h1 + dy;
        bool okx = (unsigned)ww < 128u;
        bool ok0 = okx && ((unsigned)hh0 < 128u);
        bool ok1 = okx && ((unsigned)hh1 < 128u);
        int off0 = hh0 * 128 + ww;
        int off1 = hh1 * 128 + ww;
        const float* wbase = shW + kk;
#pragma unroll 2
        for (int c = 0; c < 64; c++) {
            float v0 = ok0 ? xb[c * 16384 + off0] : 0.f;
            float v1 = ok1 ? xb[c * 16384 + off1] : 0.f;
            const float* wp = wbase + c * 9;
#pragma unroll
            for (int ch = 0; ch < 27; ch++) {
                float wv = wp[ch * 576];
                a0[ch] += v0 * wv;
                a1[ch] += v1 * wv;
            }
        }
    }

    // bilinear corner descriptors (mask & validity folded into weights)
    auto emit = [&](int p, int h, int w, const float* acc) {
#pragma unroll
        for (int k = 0; k < 9; k++) {
            float oy = acc[2 * k], ox = acc[2 * k + 1];
            float m  = 1.f / (1.f + __expf(-acc[18 + k]));
            float py = (float)(h + k / 3 - 1) + oy;
            float px = (float)(w + k % 3 - 1) + ox;
            float y0f = floorf(py), x0f = floorf(px);
            float wy1 = py - y0f, wy0 = 1.f - wy1;
            float wx1 = px - x0f, wx0 = 1.f - wx1;
            int y0 = (int)y0f, x0i = (int)x0f;
            int y1 = y0 + 1, x1i = x0i + 1;
            bool vy0 = (unsigned)y0  < 128u, vy1 = (unsigned)y1  < 128u;
            bool vx0 = (unsigned)x0i < 128u, vx1 = (unsigned)x1i < 128u;
            int cy0 = min(max(y0, 0), 127), cy1 = min(max(y1, 0), 127);
            int cx0 = min(max(x0i, 0), 127), cx1 = min(max(x1i, 0), 127);
            int4 ci; float4 cw;
            ci.x = cy0 * 128 + cx0; cw.x = (vy0 && vx0) ? m * wy0 * wx0 : 0.f;
            ci.y = cy0 * 128 + cx1; cw.y = (vy0 && vx1) ? m * wy0 * wx1 : 0.f;
            ci.z = cy1 * 128 + cx0; cw.z = (vy1 && vx0) ? m * wy1 * wx0 : 0.f;
            ci.w = cy1 * 128 + cx1; cw.w = (vy1 && vx1) ? m * wy1 * wx1 : 0.f;
            g_ci[(size_t)p * 9 + k] = ci;
            g_cw[(size_t)p * 9 + k] = cw;
        }
    };
    emit(p0,       h0, w0c, a0);
    emit(p0 + 128, h1, w0c, a1);
}

// ---------------- kernel 4: deformable gather + contraction ----------------
// CTA = 64 consecutive pixels, 256 threads. Two c-chunks of 32.
// Phase A: gather S[px][j] (j = local (c*9+k)), coalesced 128B reads from NHWC x.
// Phase B: out[64px][64o] += S[64x288] * Wq[288x64], 4px x 4o register tile/thread.
__global__ void __launch_bounds__(256) k_deform(float* __restrict__ out) {
    extern __shared__ float smem[];
    float*  sS  = smem;                          // 64*288 floats
    float*  sW  = smem + 64 * 288;               // 288*64 floats
    int4*   sCI = (int4*)(sW + 288 * 64);        // 576
    float4* sCW = (float4*)(sCI + 576);          // 576

    int t = threadIdx.x;
    int warp = t >> 5, lane = t & 31;
    int P0 = blockIdx.x << 6;
    int b  = P0 >> 14;
    int hwbase = P0 & 16383;

    for (int i = t; i < 576; i += 256) {
        sCI[i] = g_ci[(size_t)P0 * 9 + i];
        sCW[i] = g_cw[(size_t)P0 * 9 + i];
    }
    const float* xb = g_xt + (((size_t)b << 14) << 6);

    float acc[16];
#pragma unroll
    for (int i = 0; i < 16; i++) acc[i] = 0.f;
    int og = t & 15;   // o  = og*4 .. og*4+3
    int pg = t >> 4;   // px = pg*4 .. pg*4+3

    for (int jc = 0; jc < 2; jc++) {
        __syncthreads();   // protect sS/sW reuse
        for (int i = t; i < 288 * 64; i += 256) sW[i] = g_wq[jc * (288 * 64) + i];
        int c0 = jc << 5;
        // phase A: one warp per (k,px) pair, lanes span 32 channels (coalesced)
        for (int it = warp; it < 576; it += 8) {
            int k  = it / 64;
            int px = it - k * 64;
            int4   ci = sCI[px * 9 + k];
            float4 cw = sCW[px * 9 + k];
            int cc = c0 + lane;
            float v = cw.x * xb[ci.x * 64 + cc]
                    + cw.y * xb[ci.y * 64 + cc]
                    + cw.z * xb[ci.z * 64 + cc]
                    + cw.w * xb[ci.w * 64 + cc];
            sS[px * 288 + lane * 9 + k] = v;   // stride-9 lanes: conflict-free
        }
        __syncthreads();
        // phase B
#pragma unroll 2
        for (int j = 0; j < 288; j++) {
            float4 wv = *(const float4*)(sW + j * 64 + (og << 2));
            float s0 = sS[(pg * 4 + 0) * 288 + j];
            float s1 = sS[(pg * 4 + 1) * 288 + j];
            float s2 = sS[(pg * 4 + 2) * 288 + j];
            float s3 = sS[(pg * 4 + 3) * 288 + j];
            acc[0]  += s0 * wv.x;  acc[1]  += s0 * wv.y;  acc[2]  += s0 * wv.z;  acc[3]  += s0 * wv.w;
            acc[4]  += s1 * wv.x;  acc[5]  += s1 * wv.y;  acc[6]  += s1 * wv.z;  acc[7]  += s1 * wv.w;
            acc[8]  += s2 * wv.x;  acc[9]  += s2 * wv.y;  acc[10] += s2 * wv.z;  acc[11] += s2 * wv.w;
            acc[12] += s3 * wv.x;  acc[13] += s3 * wv.y;  acc[14] += s3 * wv.z;  acc[15] += s3 * wv.w;
        }
    }

    // write: 4 consecutive px per thread -> STG.128 per o
    size_t obase = (((size_t)b << 6) << 14) + hwbase + (pg << 2);
#pragma unroll
    for (int oo = 0; oo < 4; oo++) {
        int o = (og << 2) + oo;
        float4 v = make_float4(acc[oo], acc[4 + oo], acc[8 + oo], acc[12 + oo]);
        *(float4*)(out + obase + ((size_t)o << 14)) = v;
    }
}

// ---------------- launch ----------------
extern "C" void kernel_launch(void* const* d_in, const int* in_sizes, int n_in,
                              void* d_out, int out_size) {
    (void)in_sizes; (void)n_in; (void)out_size;
    const float* x      = (const float*)d_in[0];
    const float* w_conv = (const float*)d_in[1];
    const float* w_off  = (const float*)d_in[2];
    const float* w_msk  = (const float*)d_in[3];
    float* out = (float*)d_out;

    const int convSmem   = 27 * 576 * 4;                         // 62208 B
    const int deformSmem = (64 * 288 + 288 * 64) * 4 + 576 * 16 * 2;  // 165888 B
    cudaFuncSetAttribute(k_conv,   cudaFuncAttributeMaxDynamicSharedMemorySize, convSmem);
    cudaFuncSetAttribute(k_deform, cudaFuncAttributeMaxDynamicSharedMemorySize, deformSmem);

    k_transpose<<<4096, 256>>>(x);
    k_wq<<<(64 * 576 + 255) / 256, 256>>>(w_conv);
    k_conv<<<512, 128, convSmem>>>(x, w_off, w_msk);
    k_deform<<<2048, 256, deformSmem>>>(out);
}

// round 2
// speedup vs baseline: 2.3568x; 2.3568x over previous
#include <cuda_runtime.h>
#include <cstdint>

// Problem constants
#define HWsz 16384
#define Cc   64
#define Bb   8
#define NPIX (Bb * HWsz)   // 131072 pixels

// -------- scratch --------
__device__ float  g_xt[(size_t)NPIX * Cc];     // NHWC x
__device__ float  g_wq[576 * 64];              // [(c*9+k)][o]
__device__ int4   g_ci[(size_t)NPIX * 9];      // bilinear corner indices
__device__ float4 g_cw[(size_t)NPIX * 9];      // corner weights (mask folded)

// -------- f32x2 helpers --------
__device__ __forceinline__ void ffma2(unsigned long long& d, unsigned long long a, unsigned long long b) {
    asm("fma.rn.f32x2 %0, %1, %2, %0;" : "+l"(d) : "l"(a), "l"(b));
}
__device__ __forceinline__ unsigned long long pack2(float x, float y) {
    unsigned long long r; asm("mov.b64 %0, {%1, %2};" : "=l"(r) : "f"(x), "f"(y)); return r;
}
__device__ __forceinline__ float2 unpack2(unsigned long long v) {
    float2 f; asm("mov.b64 {%0, %1}, %2;" : "=f"(f.x), "=f"(f.y) : "l"(v)); return f;
}

// ---------------- kernel 1: NCHW -> NHWC ----------------
__global__ void __launch_bounds__(256) k_transpose(const float* __restrict__ x) {
    __shared__ float sh[64][33];
    int blk = blockIdx.x;
    int b   = blk >> 9;
    int hw0 = (blk & 511) << 5;
    int t = threadIdx.x;
#pragma unroll
    for (int i = 0; i < 8; i++) {
        int e = t + i * 256;
        int c = e >> 5, wp = e & 31;
        sh[c][wp] = x[((size_t)(b * 64 + c) << 14) + hw0 + wp];
    }
    __syncthreads();
#pragma unroll
    for (int i = 0; i < 8; i++) {
        int e = t + i * 256;
        int wp = e >> 6, c = e & 63;
        g_xt[(((size_t)b << 14) + hw0 + wp) * 64 + c] = sh[c][wp];
    }
}

// ---------------- kernel 2: repack w_conv ----------------
__global__ void k_wq(const float* __restrict__ w_conv) {
    int t = blockIdx.x * 256 + threadIdx.x;
    if (t < 64 * 576) {
        int o   = t / 576;
        int rem = t - o * 576;
        g_wq[rem * 64 + o] = w_conv[t];
    }
}

// ---------------- kernel 3: offset+mask conv + corner precompute ----------------
// shW2 layout: [(kk*64+c)*28 + ch], ch 0..26 real (0..17 offset, 18..26 mask), 27 = pad 0.
__global__ void __launch_bounds__(128) k_conv(const float* __restrict__ x,
                                              const float* __restrict__ w_off,
                                              const float* __restrict__ w_msk) {
    extern __shared__ float shW[];   // 9*64*28 = 16128 floats
    int t = threadIdx.x;
    for (int i = t; i < 9 * 64; i += 128) shW[i * 28 + 27] = 0.f;
    for (int i = t; i < 27 * 576; i += 128) {
        int ch = i / 576;
        int r  = i - ch * 576;     // c*9+kk
        int c  = r / 9, kk = r - c * 9;
        float v = (ch < 18) ? w_off[i] : w_msk[i - 18 * 576];
        shW[(kk * 64 + c) * 28 + ch] = v;
    }
    __syncthreads();

    int p0  = blockIdx.x * 256 + t;
    int b   = p0 >> 14;
    int hw0 = p0 & 16383;
    int h0  = hw0 >> 7, w0c = hw0 & 127;
    int h1  = h0 + 1;
    const float* xb = x + ((size_t)b << 20);

    unsigned long long a0[14], a1[14];
#pragma unroll
    for (int i = 0; i < 14; i++) { a0[i] = 0ull; a1[i] = 0ull; }

#pragma unroll 1
    for (int kk = 0; kk < 9; kk++) {
        int dy = kk / 3 - 1, dx = kk % 3 - 1;
        int hh0 = h0 + dy, ww = w0c + dx;
        int hh1 = h1 + dy;
        bool okx = (unsigned)ww < 128u;
        bool ok0 = okx && ((unsigned)hh0 < 128u);
        bool ok1 = okx && ((unsigned)hh1 < 128u);
        int off0 = hh0 * 128 + ww;
        int off1 = hh1 * 128 + ww;
        const float* wbase = shW + kk * 64 * 28;
#pragma unroll 2
        for (int c = 0; c < 64; c++) {
            float v0 = ok0 ? xb[c * 16384 + off0] : 0.f;
            float v1 = ok1 ? xb[c * 16384 + off1] : 0.f;
            unsigned long long v0d = pack2(v0, v0);
            unsigned long long v1d = pack2(v1, v1);
            const ulonglong2* wrow = (const ulonglong2*)(wbase + c * 28);
#pragma unroll
            for (int q = 0; q < 7; q++) {
                ulonglong2 wp = wrow[q];
                ffma2(a0[2 * q],     v0d, wp.x);
                ffma2(a0[2 * q + 1], v0d, wp.y);
                ffma2(a1[2 * q],     v1d, wp.x);
                ffma2(a1[2 * q + 1], v1d, wp.y);
            }
        }
    }

    float r0[28], r1[28];
#pragma unroll
    for (int q = 0; q < 14; q++) {
        float2 e0 = unpack2(a0[q]); r0[2 * q] = e0.x; r0[2 * q + 1] = e0.y;
        float2 e1 = unpack2(a1[q]); r1[2 * q] = e1.x; r1[2 * q + 1] = e1.y;
    }

    auto emit = [&](int p, int h, int w, const float* acc) {
#pragma unroll
        for (int k = 0; k < 9; k++) {
            float oy = acc[2 * k], ox = acc[2 * k + 1];
            float m  = 1.f / (1.f + __expf(-acc[18 + k]));
            float py = (float)(h + k / 3 - 1) + oy;
            float px = (float)(w + k % 3 - 1) + ox;
            float y0f = floorf(py), x0f = floorf(px);
            float wy1 = py - y0f, wy0 = 1.f - wy1;
            float wx1 = px - x0f, wx0 = 1.f - wx1;
            int y0 = (int)y0f, x0i = (int)x0f;
            int y1 = y0 + 1, x1i = x0i + 1;
            bool vy0 = (unsigned)y0  < 128u, vy1 = (unsigned)y1  < 128u;
            bool vx0 = (unsigned)x0i < 128u, vx1 = (unsigned)x1i < 128u;
            int cy0 = min(max(y0, 0), 127), cy1 = min(max(y1, 0), 127);
            int cx0 = min(max(x0i, 0), 127), cx1 = min(max(x1i, 0), 127);
            int4 ci; float4 cw;
            ci.x = cy0 * 128 + cx0; cw.x = (vy0 && vx0) ? m * wy0 * wx0 : 0.f;
            ci.y = cy0 * 128 + cx1; cw.y = (vy0 && vx1) ? m * wy0 * wx1 : 0.f;
            ci.z = cy1 * 128 + cx0; cw.z = (vy1 && vx0) ? m * wy1 * wx0 : 0.f;
            ci.w = cy1 * 128 + cx1; cw.w = (vy1 && vx1) ? m * wy1 * wx1 : 0.f;
            g_ci[(size_t)p * 9 + k] = ci;
            g_cw[(size_t)p * 9 + k] = cw;
        }
    };
    emit(p0,       h0, w0c, r0);
    emit(p0 + 128, h1, w0c, r1);
}

// ---------------- kernel 4: deformable gather + contraction ----------------
// CTA = 64 px, 256 threads. FOUR c-chunks of 16 channels (smem 93KB -> 2 CTA/SM).
// Phase B: 64px x 64o tile, thread tile 4px x 4o, j-vectorized x4, FFMA2 packed over o.
#define SSTR 148   // sS row stride (144 + 4 pad), multiple of 4 -> float4 aligned
__global__ void __launch_bounds__(256) k_deform(float* __restrict__ out) {
    extern __shared__ float smem[];
    float*  sS  = smem;                          // 64*148
    float*  sW  = smem + 64 * SSTR;              // 144*64
    int4*   sCI = (int4*)(sW + 144 * 64);        // 576
    float4* sCW = (float4*)(sCI + 576);          // 576

    int t = threadIdx.x;
    int warp = t >> 5, lane = t & 31;
    int half = lane >> 4, cl = lane & 15;
    int P0 = blockIdx.x << 6;
    int b  = P0 >> 14;
    int hwbase = P0 & 16383;

    for (int i = t; i < 576; i += 256) {
        sCI[i] = g_ci[(size_t)P0 * 9 + i];
        sCW[i] = g_cw[(size_t)P0 * 9 + i];
    }
    const float* xb = g_xt + ((size_t)b << 20);

    unsigned long long acc[4][2];
#pragma unroll
    for (int r = 0; r < 4; r++) { acc[r][0] = 0ull; acc[r][1] = 0ull; }
    int og = t & 15;   // o group: o = og*4 .. og*4+3
    int pg = t >> 4;   // px group: px = pg*4 .. pg*4+3

#pragma unroll 1
    for (int jc = 0; jc < 4; jc++) {
        __syncthreads();   // previous phase B done before overwriting sS/sW
        // load W chunk: global j = jc*144 + jl
        for (int i = t; i < 144 * 64; i += 256) sW[i] = g_wq[jc * (144 * 64) + i];
        int c0 = jc << 4;
        // gather: each warp-iter covers 2 (k,px) pairs, 16 channels per half-warp
        for (int it = warp; it < 288; it += 8) {
            int pair = it * 2 + half;        // 0..575 = k*64 + px
            int k  = pair >> 6;
            int px = pair & 63;
            int4   ci = sCI[px * 9 + k];
            float4 cw = sCW[px * 9 + k];
            int cc = c0 + cl;
            float v = cw.x * xb[ci.x * 64 + cc]
                    + cw.y * xb[ci.y * 64 + cc]
                    + cw.z * xb[ci.z * 64 + cc]
                    + cw.w * xb[ci.w * 64 + cc];
            sS[px * SSTR + cl * 9 + k] = v;   // local j = cl*9+k in [0,144)
        }
        __syncthreads();
        // phase B: S[64x144] * W[144x64]
        const float* srow0 = sS + (pg * 4 + 0) * SSTR;
        const float* srow1 = sS + (pg * 4 + 1) * SSTR;
        const float* srow2 = sS + (pg * 4 + 2) * SSTR;
        const float* srow3 = sS + (pg * 4 + 3) * SSTR;
#pragma unroll 4
        for (int j = 0; j < 144; j += 4) {
            ulonglong2 w0 = ((const ulonglong2*)(sW + (j + 0) * 64))[og];
            ulonglong2 w1 = ((const ulonglong2*)(sW + (j + 1) * 64))[og];
            ulonglong2 w2 = ((const ulonglong2*)(sW + (j + 2) * 64))[og];
            ulonglong2 w3 = ((const ulonglong2*)(sW + (j + 3) * 64))[og];
            float4 s0 = *(const float4*)(srow0 + j);
            float4 s1 = *(const float4*)(srow1 + j);
            float4 s2 = *(const float4*)(srow2 + j);
            float4 s3 = *(const float4*)(srow3 + j);
#define STEP(r, s)                                            \
            {                                                 \
                unsigned long long d;                         \
                d = pack2(s.x, s.x); ffma2(acc[r][0], d, w0.x); ffma2(acc[r][1], d, w0.y); \
                d = pack2(s.y, s.y); ffma2(acc[r][0], d, w1.x); ffma2(acc[r][1], d, w1.y); \
                d = pack2(s.z, s.z); ffma2(acc[r][0], d, w2.x); ffma2(acc[r][1], d, w2.y); \
                d = pack2(s.w, s.w); ffma2(acc[r][0], d, w3.x); ffma2(acc[r][1], d, w3.y); \
            }
            STEP(0, s0) STEP(1, s1) STEP(2, s2) STEP(3, s3)
#undef STEP
        }
    }

    // unpack: acc[r][0] -> o = og*4+0, og*4+1 ; acc[r][1] -> og*4+2, og*4+3
    float2 u[4][2];
#pragma unroll
    for (int r = 0; r < 4; r++) { u[r][0] = unpack2(acc[r][0]); u[r][1] = unpack2(acc[r][1]); }

    size_t obase = ((size_t)b << 20) + hwbase + (pg << 2);
    int o0 = og << 2;
    *(float4*)(out + obase + (size_t)(o0 + 0) * 16384) = make_float4(u[0][0].x, u[1][0].x, u[2][0].x, u[3][0].x);
    *(float4*)(out + obase + (size_t)(o0 + 1) * 16384) = make_float4(u[0][0].y, u[1][0].y, u[2][0].y, u[3][0].y);
    *(float4*)(out + obase + (size_t)(o0 + 2) * 16384) = make_float4(u[0][1].x, u[1][1].x, u[2][1].x, u[3][1].x);
    *(float4*)(out + obase + (size_t)(o0 + 3) * 16384) = make_float4(u[0][1].y, u[1][1].y, u[2][1].y, u[3][1].y);
}

// ---------------- launch ----------------
extern "C" void kernel_launch(void* const* d_in, const int* in_sizes, int n_in,
                              void* d_out, int out_size) {
    (void)in_sizes; (void)n_in; (void)out_size;
    const float* x      = (const float*)d_in[0];
    const float* w_conv = (const float*)d_in[1];
    const float* w_off  = (const float*)d_in[2];
    const float* w_msk  = (const float*)d_in[3];
    float* out = (float*)d_out;

    const int convSmem   = 9 * 64 * 28 * 4;                        // 64512 B
    const int deformSmem = (64 * SSTR + 144 * 64) * 4 + 576 * 32;  // 93184 B
    cudaFuncSetAttribute(k_conv,   cudaFuncAttributeMaxDynamicSharedMemorySize, convSmem);
    cudaFuncSetAttribute(k_deform, cudaFuncAttributeMaxDynamicSharedMemorySize, deformSmem);

    k_transpose<<<4096, 256>>>(x);
    k_wq<<<(64 * 576 + 255) / 256, 256>>>(w_conv);
    k_conv<<<512, 128, convSmem>>>(x, w_off, w_msk);
    k_deform<<<2048, 256, deformSmem>>>(out);
}